// round 8
// baseline (speedup 1.0000x reference)
#include <cuda_runtime.h>
#include <cuda_bf16.h>
#include <math.h>
#include <stdint.h>

// Problem constants
#define BATCH 2
#define SEQ   1024
#define HID   5120
#define NHEAD 40
#define HDIM  128
#define QKV_N (3*HID)          // 15360
#define MROWS (BATCH*SEQ)      // 2048

// ---------------------------------------------------------------------------
// Scratch
// ---------------------------------------------------------------------------
__device__ __nv_bfloat16 g_qkvh[(size_t)MROWS * QKV_N];
__device__ __nv_bfloat16 g_qkvl[(size_t)MROWS * QKV_N];
__device__ __nv_bfloat16 g_hh[(size_t)MROWS * HID];
__device__ __nv_bfloat16 g_hl[(size_t)MROWS * HID];
__device__ __nv_bfloat16 g_ah[(size_t)MROWS * HID];
__device__ __nv_bfloat16 g_al[(size_t)MROWS * HID];
__device__ __nv_bfloat16 g_wph[(size_t)QKV_N * HID];
__device__ __nv_bfloat16 g_wpl[(size_t)QKV_N * HID];
__device__ __nv_bfloat16 g_woh[(size_t)HID * HID];
__device__ __nv_bfloat16 g_wol[(size_t)HID * HID];

// ---------------------------------------------------------------------------
// PTX helpers (compute_103-safe)
// ---------------------------------------------------------------------------
__device__ __forceinline__ uint32_t smem_u32(const void* p) {
    uint32_t a;
    asm("{ .reg .u64 t; cvta.to.shared.u64 t, %1; cvt.u32.u64 %0, t; }"
        : "=r"(a) : "l"(p));
    return a;
}

#define CP_ASYNC16(dst, src) \
    asm volatile("cp.async.cg.shared.global [%0], [%1], 16;" \
        :: "r"(dst), "l"(src))
#define CP_COMMIT() asm volatile("cp.async.commit_group;" ::: "memory")
#define CP_WAIT(n)  asm volatile("cp.async.wait_group %0;" :: "n"(n) : "memory")

__device__ __forceinline__ void ldm_x4(uint32_t* r, uint32_t addr) {
    asm volatile("ldmatrix.sync.aligned.m8n8.x4.shared.b16 {%0,%1,%2,%3}, [%4];"
        : "=r"(r[0]), "=r"(r[1]), "=r"(r[2]), "=r"(r[3]) : "r"(addr));
}
__device__ __forceinline__ void ldm_x4_t(uint32_t* r, uint32_t addr) {
    asm volatile("ldmatrix.sync.aligned.m8n8.x4.trans.shared.b16 {%0,%1,%2,%3}, [%4];"
        : "=r"(r[0]), "=r"(r[1]), "=r"(r[2]), "=r"(r[3]) : "r"(addr));
}

__device__ __forceinline__ void mma_bf16(float* d, const uint32_t* a,
                                         uint32_t b0, uint32_t b1) {
    asm volatile(
        "mma.sync.aligned.m16n8k16.row.col.f32.bf16.bf16.f32 "
        "{%0,%1,%2,%3}, {%4,%5,%6,%7}, {%8,%9}, {%0,%1,%2,%3};"
        : "+f"(d[0]), "+f"(d[1]), "+f"(d[2]), "+f"(d[3])
        : "r"(a[0]), "r"(a[1]), "r"(a[2]), "r"(a[3]), "r"(b0), "r"(b1));
}

// ---------------------------------------------------------------------------
// fp32 -> (bf16 hi, bf16 lo) split
// ---------------------------------------------------------------------------
__global__ void split_bf16(const float* __restrict__ x,
                           __nv_bfloat16* __restrict__ hi,
                           __nv_bfloat16* __restrict__ lo, size_t n4)
{
    size_t i = (size_t)blockIdx.x * blockDim.x + threadIdx.x;
    if (i >= n4) return;
    float4 v = ((const float4*)x)[i];
    __nv_bfloat16 h0 = __float2bfloat16(v.x);
    __nv_bfloat16 h1 = __float2bfloat16(v.y);
    __nv_bfloat16 h2 = __float2bfloat16(v.z);
    __nv_bfloat16 h3 = __float2bfloat16(v.w);
    __nv_bfloat162 H0; H0.x = h0; H0.y = h1;
    __nv_bfloat162 H1; H1.x = h2; H1.y = h3;
    ((__nv_bfloat162*)hi)[2*i]   = H0;
    ((__nv_bfloat162*)hi)[2*i+1] = H1;
    __nv_bfloat162 L0, L1;
    L0.x = __float2bfloat16(v.x - __bfloat162float(h0));
    L0.y = __float2bfloat16(v.y - __bfloat162float(h1));
    L1.x = __float2bfloat16(v.z - __bfloat162float(h2));
    L1.y = __float2bfloat16(v.w - __bfloat162float(h3));
    ((__nv_bfloat162*)lo)[2*i]   = L0;
    ((__nv_bfloat162*)lo)[2*i+1] = L1;
}

// ---------------------------------------------------------------------------
// WIDE bf16x3 HMMA GEMM: CTA 128x256, 8 warps (2M x 4N), warp tile 64x64.
// MMA:LDSM ratio 6:1. 2-stage cp.async pipeline (2x110KB smem).
// Writes bf16 hi/lo split output (for GEMM1 -> attention).
// ---------------------------------------------------------------------------
#define WBM 128
#define WBN 256
#define WBK 64
#define WROWB 144
#define W_ATILE (128 * WROWB)            // 18432
#define W_BTILE (256 * WROWB)            // 36864
#define W_STAGE (2*W_ATILE + 2*W_BTILE)  // 110592
#define W_SMEM  (2 * W_STAGE)            // 221184

__global__ __launch_bounds__(256, 1)
void gemm_wide(const __nv_bfloat16* __restrict__ Ah, const __nv_bfloat16* __restrict__ Al,
               const __nv_bfloat16* __restrict__ Bh, const __nv_bfloat16* __restrict__ Bl,
               __nv_bfloat16* __restrict__ Ch, __nv_bfloat16* __restrict__ Cl,
               int M, int N, int K)
{
    extern __shared__ char smem[];
    const uint32_t sbase = smem_u32(smem);
    const int tid  = threadIdx.x;
    const int wid  = tid >> 5;
    const int lane = tid & 31;
    const int wm = wid & 1;          // 0..1 -> M offset wm*64
    const int wn = wid >> 1;         // 0..3 -> N offset wn*64
    const int m0 = blockIdx.x * WBM;
    const int n0 = blockIdx.y * WBN;
    const int NCH = K / WBK;

    // stage loader: 6144 16B chunks, 24 per thread
    auto load_stage = [&](int s, int kc) {
        const int k0 = kc * WBK;
#pragma unroll
        for (int j = 0; j < 24; j++) {
            int id = tid + j * 256;          // 0..6143
            const __nv_bfloat16* src;
            uint32_t dstoff;
            int row, c16;
            if (id < 2048) {                 // A hi/lo
                int t2  = id >> 10;          // 0=Ah 1=Al
                int idx = id & 1023;
                row = idx >> 3; c16 = idx & 7;
                src = (t2 ? Al : Ah) + (size_t)(m0 + row) * K + k0 + c16 * 8;
                dstoff = t2 * W_ATILE + row * WROWB + c16 * 16;
            } else {                         // B hi/lo
                int id2 = id - 2048;
                int t2  = id2 >> 11;         // 0=Bh 1=Bl
                int idx = id2 & 2047;
                row = idx >> 3; c16 = idx & 7;
                src = (t2 ? Bl : Bh) + (size_t)(n0 + row) * K + k0 + c16 * 8;
                dstoff = 2 * W_ATILE + t2 * W_BTILE + row * WROWB + c16 * 16;
            }
            CP_ASYNC16(sbase + s * W_STAGE + dstoff, src);
        }
        CP_COMMIT();
    };

    float acc[4][8][4];
#pragma unroll
    for (int mi = 0; mi < 4; mi++)
#pragma unroll
        for (int nj = 0; nj < 8; nj++)
#pragma unroll
            for (int q = 0; q < 4; q++) acc[mi][nj][q] = 0.f;

    load_stage(0, 0);
    if (NCH > 1) load_stage(1, 1);

    const int lr = lane & 15;
    const int lc = (lane >> 4) * 16;
    const uint32_t rowA = (wm * 64 + lr) * WROWB + lc;
    const uint32_t rowB = (wn * 64 + lr) * WROWB + lc;

    for (int c = 0; c < NCH; c++) {
        CP_WAIT(1);
        __syncthreads();

        const uint32_t st  = sbase + (c & 1) * W_STAGE;
        const uint32_t sAh = st;
        const uint32_t sAl = st + W_ATILE;
        const uint32_t sBh = st + 2 * W_ATILE;
        const uint32_t sBl = st + 2 * W_ATILE + W_BTILE;

#pragma unroll
        for (int kk = 0; kk < 4; kk++) {
            const uint32_t koff = kk * 32;
            uint32_t ahf[4][4], alf[4][4];
#pragma unroll
            for (int mi = 0; mi < 4; mi++) {
                uint32_t ra = rowA + mi * 16 * WROWB + koff;
                ldm_x4(ahf[mi], sAh + ra);
                ldm_x4(alf[mi], sAl + ra);
            }
#pragma unroll
            for (int nj = 0; nj < 4; nj++) {
                const uint32_t rb = rowB + nj * 16 * WROWB + koff;
                uint32_t bhf[4], blf[4];
                ldm_x4(bhf, sBh + rb);
                ldm_x4(blf, sBl + rb);
                // term 1: Ah*Bh (8 independent accs)
#pragma unroll
                for (int mi = 0; mi < 4; mi++) {
                    mma_bf16(acc[mi][2*nj],   ahf[mi], bhf[0], bhf[2]);
                    mma_bf16(acc[mi][2*nj+1], ahf[mi], bhf[1], bhf[3]);
                }
                // term 2: Ah*Bl
#pragma unroll
                for (int mi = 0; mi < 4; mi++) {
                    mma_bf16(acc[mi][2*nj],   ahf[mi], blf[0], blf[2]);
                    mma_bf16(acc[mi][2*nj+1], ahf[mi], blf[1], blf[3]);
                }
                // term 3: Al*Bh
#pragma unroll
                for (int mi = 0; mi < 4; mi++) {
                    mma_bf16(acc[mi][2*nj],   alf[mi], bhf[0], bhf[2]);
                    mma_bf16(acc[mi][2*nj+1], alf[mi], bhf[1], bhf[3]);
                }
            }
        }

        __syncthreads();
        if (c + 2 < NCH) load_stage(c & 1, c + 2);
    }

    const int g  = lane >> 2;
    const int cc = (lane & 3) * 2;
#pragma unroll
    for (int mi = 0; mi < 4; mi++) {
        const int rbase = m0 + wm * 64 + mi * 16;
#pragma unroll
        for (int nj = 0; nj < 8; nj++) {
            const int cbase = n0 + wn * 64 + nj * 8 + cc;
#pragma unroll
            for (int rr = 0; rr < 2; rr++) {
                float x0 = acc[mi][nj][2*rr], x1 = acc[mi][nj][2*rr+1];
                __nv_bfloat16 h0 = __float2bfloat16(x0);
                __nv_bfloat16 h1 = __float2bfloat16(x1);
                __nv_bfloat162 H; H.x = h0; H.y = h1;
                __nv_bfloat162 L;
                L.x = __float2bfloat16(x0 - __bfloat162float(h0));
                L.y = __float2bfloat16(x1 - __bfloat162float(h1));
                size_t off = (size_t)(rbase + g + 8*rr) * N + cbase;
                *(__nv_bfloat162*)&Ch[off] = H;
                *(__nv_bfloat162*)&Cl[off] = L;
            }
        }
    }
}

// ---------------------------------------------------------------------------
// 128x128 bf16x3 HMMA GEMM (round-6 mainloop) — used for GEMM2 (fp32 out)
// ---------------------------------------------------------------------------
#define BM 128
#define BN 128
#define BK 64
#define ROWB 144
#define TILEB (128 * ROWB)
#define STAGEB (4 * TILEB)
#define NSTAGE 3
#define GEMM_SMEM_BYTES (NSTAGE * STAGEB)   // 221184
#define GTHREADS 256

__global__ __launch_bounds__(GTHREADS, 1)
void gemm_hmma(const __nv_bfloat16* __restrict__ Ah, const __nv_bfloat16* __restrict__ Al,
               const __nv_bfloat16* __restrict__ Bh, const __nv_bfloat16* __restrict__ Bl,
               float* __restrict__ Cf, int M, int N, int K)
{
    extern __shared__ char smem[];
    const uint32_t sbase = smem_u32(smem);
    const int tid  = threadIdx.x;
    const int wid  = tid >> 5;
    const int lane = tid & 31;
    const int wm = wid & 3;
    const int wn = wid >> 2;
    const int m0 = blockIdx.x * BM;
    const int n0 = blockIdx.y * BN;
    const int NCH = K / BK;

    auto load_stage = [&](int s, int kc) {
        const int k0 = kc * BK;
#pragma unroll
        for (int j = 0; j < 16; j++) {
            int id   = tid + j * GTHREADS;
            int tile = id >> 10;
            int idx  = id & 1023;
            int row  = idx >> 3;
            int c16  = idx & 7;
            const __nv_bfloat16* sb =
                (tile == 0) ? Ah : (tile == 1) ? Al : (tile == 2) ? Bh : Bl;
            int grow = ((tile < 2) ? m0 : n0) + row;
            const void* src = sb + (size_t)grow * K + k0 + c16 * 8;
            uint32_t dst = sbase + s * STAGEB + tile * TILEB + row * ROWB + c16 * 16;
            CP_ASYNC16(dst, src);
        }
        CP_COMMIT();
    };

    float acc[2][8][4];
#pragma unroll
    for (int mi = 0; mi < 2; mi++)
#pragma unroll
        for (int nj = 0; nj < 8; nj++)
#pragma unroll
            for (int q = 0; q < 4; q++) acc[mi][nj][q] = 0.f;

    load_stage(0, 0);
    if (NCH > 1) load_stage(1, 1);

    const int lr = lane & 15;
    const int lc = (lane >> 4) * 16;
    const uint32_t rowA = (wm * 32 + lr) * ROWB + lc;
    const uint32_t rowB = (wn * 64 + lr) * ROWB + lc;

    int sidx = 0;
    for (int c = 0; c < NCH; c++) {
        CP_WAIT(1);
        __syncthreads();
        if (c + 2 < NCH) {
            int s2 = sidx + 2; if (s2 >= NSTAGE) s2 -= NSTAGE;
            load_stage(s2, c + 2);
        }

        const uint32_t st  = sbase + sidx * STAGEB;
        const uint32_t sAh = st;
        const uint32_t sAl = st + TILEB;
        const uint32_t sBh = st + 2 * TILEB;
        const uint32_t sBl = st + 3 * TILEB;

#pragma unroll
        for (int kk = 0; kk < 4; kk++) {
            const uint32_t koff = kk * 32;
            uint32_t ahf[2][4], alf[2][4], bhf[4][4], blf[4][4];
#pragma unroll
            for (int mi = 0; mi < 2; mi++) {
                uint32_t ra = rowA + mi * 16 * ROWB + koff;
                ldm_x4(ahf[mi], sAh + ra);
                ldm_x4(alf[mi], sAl + ra);
            }
#pragma unroll
            for (int nj = 0; nj < 4; nj++) {
                uint32_t rb = rowB + nj * 16 * ROWB + koff;
                ldm_x4(bhf[nj], sBh + rb);
                ldm_x4(blf[nj], sBl + rb);
            }
#pragma unroll
            for (int mi = 0; mi < 2; mi++)
#pragma unroll
                for (int nj = 0; nj < 4; nj++) {
                    mma_bf16(acc[mi][2*nj],   ahf[mi], bhf[nj][0], bhf[nj][2]);
                    mma_bf16(acc[mi][2*nj+1], ahf[mi], bhf[nj][1], bhf[nj][3]);
                }
#pragma unroll
            for (int mi = 0; mi < 2; mi++)
#pragma unroll
                for (int nj = 0; nj < 4; nj++) {
                    mma_bf16(acc[mi][2*nj],   ahf[mi], blf[nj][0], blf[nj][2]);
                    mma_bf16(acc[mi][2*nj+1], ahf[mi], blf[nj][1], blf[nj][3]);
                }
#pragma unroll
            for (int mi = 0; mi < 2; mi++)
#pragma unroll
                for (int nj = 0; nj < 4; nj++) {
                    mma_bf16(acc[mi][2*nj],   alf[mi], bhf[nj][0], bhf[nj][2]);
                    mma_bf16(acc[mi][2*nj+1], alf[mi], bhf[nj][1], bhf[nj][3]);
                }
        }
        if (++sidx >= NSTAGE) sidx -= NSTAGE;
    }

    const int g  = lane >> 2;
    const int cc = (lane & 3) * 2;
#pragma unroll
    for (int mi = 0; mi < 2; mi++) {
        const int rbase = m0 + wm * 32 + mi * 16;
#pragma unroll
        for (int nj = 0; nj < 8; nj++) {
            const int cbase = n0 + wn * 64 + nj * 8 + cc;
            float2 v0 = make_float2(acc[mi][nj][0], acc[mi][nj][1]);
            float2 v1 = make_float2(acc[mi][nj][2], acc[mi][nj][3]);
            *(float2*)&Cf[(size_t)(rbase + g) * N + cbase]     = v0;
            *(float2*)&Cf[(size_t)(rbase + g + 8) * N + cbase] = v1;
        }
    }
}

// ---------------------------------------------------------------------------
// HMMA flash attention (round 7, unchanged)
// ---------------------------------------------------------------------------
#define AROW 272
#define ATILE (64 * AROW)
#define PROW 144
#define PTILE (64 * PROW)
#define KSTAGE (4 * ATILE)
#define ATTN_SMEM (2*ATILE + 2*KSTAGE + 2*PTILE)

__global__ __launch_bounds__(128, 1)
void attn_hmma(const __nv_bfloat16* __restrict__ QKVh,
               const __nv_bfloat16* __restrict__ QKVl,
               __nv_bfloat16* __restrict__ Oh,
               __nv_bfloat16* __restrict__ Ol)
{
    extern __shared__ char smem[];
    const uint32_t sb = smem_u32(smem);
    const int tid = threadIdx.x, wid = tid >> 5, lane = tid & 31;
    const int qt = blockIdx.x, h = blockIdx.y, b = blockIdx.z;
    const int q0 = qt * 64;
    const int lr = lane & 15, lc = (lane >> 4) * 16;
    const int g = lane >> 2, t = lane & 3;

    const uint32_t QH_ = sb, QL_ = sb + ATILE;
    const uint32_t KST = sb + 2 * ATILE;
    const uint32_t PH_ = sb + 2 * ATILE + 2 * KSTAGE;
    const uint32_t PL_ = PH_ + PTILE;

#pragma unroll
    for (int j = 0; j < 8; j++) {
        int id = tid + j * 128;
        int row = id >> 4, c16 = id & 15;
        size_t goff = (size_t)(b * SEQ + q0 + row) * QKV_N + h * HDIM + c16 * 8;
        CP_ASYNC16(QH_ + row * AROW + c16 * 16, QKVh + goff);
        CP_ASYNC16(QL_ + row * AROW + c16 * 16, QKVl + goff);
    }
    CP_COMMIT();

    auto load_kv = [&](int s, int kt) {
        const uint32_t base = KST + s * KSTAGE;
        const int k0 = kt * 64;
#pragma unroll
        for (int j = 0; j < 8; j++) {
            int id = tid + j * 128;
            int row = id >> 4, c16 = id & 15;
            size_t grow = (size_t)(b * SEQ + k0 + row) * QKV_N;
            size_t koff = grow + HID     + h * HDIM + c16 * 8;
            size_t voff = grow + 2 * HID + h * HDIM + c16 * 8;
            uint32_t d = row * AROW + c16 * 16;
            CP_ASYNC16(base + d,             QKVh + koff);
            CP_ASYNC16(base + ATILE + d,     QKVl + koff);
            CP_ASYNC16(base + 2 * ATILE + d, QKVh + voff);
            CP_ASYNC16(base + 3 * ATILE + d, QKVl + voff);
        }
        CP_COMMIT();
    };

    load_kv(0, 0);

    const float LOG2E = 1.4426950408889634f;
    const float sscale = 0.08838834764831845f * LOG2E;
    const float slope = (h < 32) ? exp2f(-0.25f * (float)(h + 1))
                                 : exp2f(-0.125f * (float)(2 * (h - 32) + 1));
    const float slope2 = slope * LOG2E;

    const int row0 = q0 + wid * 16 + g;
    const int row1 = row0 + 8;

    float m0v = -1e30f, m1v = -1e30f, l0 = 0.f, l1 = 0.f;
    float o[16][4];
#pragma unroll
    for (int i = 0; i < 16; i++)
#pragma unroll
        for (int q = 0; q < 4; q++) o[i][q] = 0.f;

    for (int kt = 0; kt <= qt; kt++) {
        const bool more = (kt + 1 <= qt);
        if (more) load_kv((kt + 1) & 1, kt + 1);
        if (more) { CP_WAIT(1); } else { CP_WAIT(0); }
        __syncthreads();

        const uint32_t KB  = KST + (kt & 1) * KSTAGE;
        const uint32_t KHB = KB, KLB = KB + ATILE;
        const uint32_t VHB = KB + 2 * ATILE, VLB = KB + 3 * ATILE;

        float sacc[8][4];
#pragma unroll
        for (int nj = 0; nj < 8; nj++)
#pragma unroll
            for (int q = 0; q < 4; q++) sacc[nj][q] = 0.f;

#pragma unroll
        for (int dd = 0; dd < 8; dd++) {
            const uint32_t ra = (wid * 16 + lr) * AROW + dd * 32 + lc;
            uint32_t qhf[4], qlf[4];
            ldm_x4(qhf, QH_ + ra);
            ldm_x4(qlf, QL_ + ra);
            uint32_t khf[4][4], klf[4][4];
#pragma unroll
            for (int v = 0; v < 4; v++) {
                const uint32_t rb = (v * 16 + lr) * AROW + dd * 32 + lc;
                ldm_x4(khf[v], KHB + rb);
                ldm_x4(klf[v], KLB + rb);
            }
#pragma unroll
            for (int v = 0; v < 4; v++) {
                mma_bf16(sacc[2*v],   qhf, khf[v][0], khf[v][2]);
                mma_bf16(sacc[2*v+1], qhf, khf[v][1], khf[v][3]);
            }
#pragma unroll
            for (int v = 0; v < 4; v++) {
                mma_bf16(sacc[2*v],   qhf, klf[v][0], klf[v][2]);
                mma_bf16(sacc[2*v+1], qhf, klf[v][1], klf[v][3]);
            }
#pragma unroll
            for (int v = 0; v < 4; v++) {
                mma_bf16(sacc[2*v],   qlf, khf[v][0], khf[v][2]);
                mma_bf16(sacc[2*v+1], qlf, khf[v][1], khf[v][3]);
            }
        }

        const int k0 = kt * 64;
        const bool diag = (kt == qt);
        float rmax0 = -1e30f, rmax1 = -1e30f;
#pragma unroll
        for (int nj = 0; nj < 8; nj++) {
#pragma unroll
            for (int e = 0; e < 2; e++) {
                const int col = k0 + nj * 8 + 2 * t + e;
                float v0 = sacc[nj][e]     * sscale + slope2 * (float)col;
                float v1 = sacc[nj][2 + e] * sscale + slope2 * (float)col;
                if (diag) {
                    if (col > row0) v0 = -1e30f;
                    if (col > row1) v1 = -1e30f;
                }
                sacc[nj][e] = v0; sacc[nj][2 + e] = v1;
                rmax0 = fmaxf(rmax0, v0); rmax1 = fmaxf(rmax1, v1);
            }
        }
        rmax0 = fmaxf(rmax0, __shfl_xor_sync(0xffffffffu, rmax0, 1));
        rmax0 = fmaxf(rmax0, __shfl_xor_sync(0xffffffffu, rmax0, 2));
        rmax1 = fmaxf(rmax1, __shfl_xor_sync(0xffffffffu, rmax1, 1));
        rmax1 = fmaxf(rmax1, __shfl_xor_sync(0xffffffffu, rmax1, 2));

        const float mn0 = fmaxf(m0v, rmax0), mn1 = fmaxf(m1v, rmax1);
        const float al0 = exp2f(m0v - mn0),  al1 = exp2f(m1v - mn1);
        m0v = mn0; m1v = mn1;

        float ps0 = 0.f, ps1 = 0.f;
#pragma unroll
        for (int nj = 0; nj < 8; nj++) {
#pragma unroll
            for (int e = 0; e < 2; e++) {
                float p0 = exp2f(sacc[nj][e]     - mn0);
                float p1 = exp2f(sacc[nj][2 + e] - mn1);
                sacc[nj][e] = p0; sacc[nj][2 + e] = p1;
                ps0 += p0; ps1 += p1;
            }
        }
        ps0 += __shfl_xor_sync(0xffffffffu, ps0, 1);
        ps0 += __shfl_xor_sync(0xffffffffu, ps0, 2);
        ps1 += __shfl_xor_sync(0xffffffffu, ps1, 1);
        ps1 += __shfl_xor_sync(0xffffffffu, ps1, 2);
        l0 = l0 * al0 + ps0;
        l1 = l1 * al1 + ps1;

#pragma unroll
        for (int i = 0; i < 16; i++) {
            o[i][0] *= al0; o[i][1] *= al0;
            o[i][2] *= al1; o[i][3] *= al1;
        }

#pragma unroll
        for (int nj = 0; nj < 8; nj++) {
#pragma unroll
            for (int rr = 0; rr < 2; rr++) {
                float x0 = sacc[nj][2*rr], x1 = sacc[nj][2*rr + 1];
                __nv_bfloat16 h0 = __float2bfloat16(x0);
                __nv_bfloat16 h1 = __float2bfloat16(x1);
                __nv_bfloat162 H; H.x = h0; H.y = h1;
                __nv_bfloat162 L;
                L.x = __float2bfloat16(x0 - __bfloat162float(h0));
                L.y = __float2bfloat16(x1 - __bfloat162float(h1));
                uint32_t off = (wid * 16 + g + 8 * rr) * PROW + (nj * 8 + 2 * t) * 2;
                *(__nv_bfloat162*)(smem + (PH_ - sb) + off) = H;
                *(__nv_bfloat162*)(smem + (PL_ - sb) + off) = L;
            }
        }
        __syncwarp();

#pragma unroll
        for (int ks = 0; ks < 4; ks++) {
            const uint32_t pa = (wid * 16 + lr) * PROW + ks * 32 + lc;
            uint32_t phf[4], plf[4];
            ldm_x4(phf, PH_ + pa);
            ldm_x4(plf, PL_ + pa);
#pragma unroll
            for (int nn = 0; nn < 8; nn++) {
                const uint32_t va = (ks * 16 + lr) * AROW + nn * 32 + lc;
                uint32_t vhf[4], vlf[4];
                ldm_x4_t(vhf, VHB + va);
                ldm_x4_t(vlf, VLB + va);
                mma_bf16(o[2*nn],   phf, vhf[0], vhf[1]);
                mma_bf16(o[2*nn+1], phf, vhf[2], vhf[3]);
                mma_bf16(o[2*nn],   phf, vlf[0], vlf[1]);
                mma_bf16(o[2*nn+1], phf, vlf[2], vlf[3]);
                mma_bf16(o[2*nn],   plf, vhf[0], vhf[1]);
                mma_bf16(o[2*nn+1], plf, vhf[2], vhf[3]);
            }
        }
        __syncthreads();
    }

    const float inv0 = 1.0f / l0, inv1 = 1.0f / l1;
#pragma unroll
    for (int i = 0; i < 16; i++) {
        const int col = h * HDIM + i * 8 + 2 * t;
#pragma unroll
        for (int rr = 0; rr < 2; rr++) {
            const float inv = rr ? inv1 : inv0;
            const int row = rr ? row1 : row0;
            float x0 = o[i][2*rr] * inv, x1 = o[i][2*rr + 1] * inv;
            __nv_bfloat16 h0 = __float2bfloat16(x0);
            __nv_bfloat16 h1 = __float2bfloat16(x1);
            __nv_bfloat162 H; H.x = h0; H.y = h1;
            __nv_bfloat162 L;
            L.x = __float2bfloat16(x0 - __bfloat162float(h0));
            L.y = __float2bfloat16(x1 - __bfloat162float(h1));
            size_t off = (size_t)(b * SEQ + row) * HID + col;
            *(__nv_bfloat162*)&Oh[off] = H;
            *(__nv_bfloat162*)&Ol[off] = L;
        }
    }
}

// ---------------------------------------------------------------------------
// Launch
// ---------------------------------------------------------------------------
extern "C" void kernel_launch(void* const* d_in, const int* in_sizes, int n_in,
                              void* d_out, int out_size)
{
    const float* hidden = (const float*)d_in[0];
    const float* W_pack = (const float*)d_in[1];
    const float* W_o    = (const float*)d_in[2];
    float* out = (float*)d_out;

    __nv_bfloat16 *qkvh, *qkvl, *hh, *hl, *ah, *al, *wph, *wpl, *woh, *wol;
    cudaGetSymbolAddress((void**)&qkvh, g_qkvh);
    cudaGetSymbolAddress((void**)&qkvl, g_qkvl);
    cudaGetSymbolAddress((void**)&hh,  g_hh);
    cudaGetSymbolAddress((void**)&hl,  g_hl);
    cudaGetSymbolAddress((void**)&ah,  g_ah);
    cudaGetSymbolAddress((void**)&al,  g_al);
    cudaGetSymbolAddress((void**)&wph, g_wph);
    cudaGetSymbolAddress((void**)&wpl, g_wpl);
    cudaGetSymbolAddress((void**)&woh, g_woh);
    cudaGetSymbolAddress((void**)&wol, g_wol);

    cudaFuncSetAttribute(gemm_wide, cudaFuncAttributeMaxDynamicSharedMemorySize,
                         W_SMEM);
    cudaFuncSetAttribute(gemm_hmma, cudaFuncAttributeMaxDynamicSharedMemorySize,
                         GEMM_SMEM_BYTES);
    cudaFuncSetAttribute(attn_hmma, cudaFuncAttributeMaxDynamicSharedMemorySize,
                         ATTN_SMEM);

    {
        size_t n4;
        n4 = (size_t)QKV_N * HID / 4;
        split_bf16<<<(unsigned)((n4 + 255) / 256), 256>>>(W_pack, wph, wpl, n4);
        n4 = (size_t)HID * HID / 4;
        split_bf16<<<(unsigned)((n4 + 255) / 256), 256>>>(W_o, woh, wol, n4);
        n4 = (size_t)MROWS * HID / 4;
        split_bf16<<<(unsigned)((n4 + 255) / 256), 256>>>(hidden, hh, hl, n4);
    }

    // GEMM1 (wide tile): qkv = hidden @ W_pack^T, bf16 hi/lo output
    gemm_wide<<<dim3(MROWS/WBM, QKV_N/WBN), 256, W_SMEM>>>(
        hh, hl, wph, wpl, qkvh, qkvl, MROWS, QKV_N, HID);

    // Attention
    attn_hmma<<<dim3(SEQ/64, NHEAD, BATCH), 128, ATTN_SMEM>>>(qkvh, qkvl, ah, al);

    // GEMM2 (128x128): out = attn @ W_o^T, fp32 output
    gemm_hmma<<<dim3(MROWS/BM, HID/BN), GTHREADS, GEMM_SMEM_BYTES>>>(
        ah, al, woh, wol, out, MROWS, HID, HID);
}

// round 9
// speedup vs baseline: 1.0169x; 1.0169x over previous
#include <cuda_runtime.h>
#include <cuda_bf16.h>
#include <math.h>
#include <stdint.h>

// Problem constants
#define BATCH 2
#define SEQ   1024
#define HID   5120
#define NHEAD 40
#define HDIM  128
#define QKV_N (3*HID)          // 15360
#define MROWS (BATCH*SEQ)      // 2048

// ---------------------------------------------------------------------------
// Scratch
// ---------------------------------------------------------------------------
__device__ __nv_bfloat16 g_qkvh[(size_t)MROWS * QKV_N];
__device__ __nv_bfloat16 g_qkvl[(size_t)MROWS * QKV_N];
__device__ __nv_bfloat16 g_hh[(size_t)MROWS * HID];
__device__ __nv_bfloat16 g_hl[(size_t)MROWS * HID];
__device__ __nv_bfloat16 g_ah[(size_t)MROWS * HID];
__device__ __nv_bfloat16 g_al[(size_t)MROWS * HID];
__device__ __nv_bfloat16 g_wph[(size_t)QKV_N * HID];
__device__ __nv_bfloat16 g_wpl[(size_t)QKV_N * HID];
__device__ __nv_bfloat16 g_woh[(size_t)HID * HID];
__device__ __nv_bfloat16 g_wol[(size_t)HID * HID];

// ---------------------------------------------------------------------------
// PTX helpers (compute_103-safe)
// ---------------------------------------------------------------------------
__device__ __forceinline__ uint32_t smem_u32(const void* p) {
    uint32_t a;
    asm("{ .reg .u64 t; cvta.to.shared.u64 t, %1; cvt.u32.u64 %0, t; }"
        : "=r"(a) : "l"(p));
    return a;
}

#define CP_ASYNC16(dst, src) \
    asm volatile("cp.async.cg.shared.global [%0], [%1], 16;" \
        :: "r"(dst), "l"(src))
#define CP_COMMIT() asm volatile("cp.async.commit_group;" ::: "memory")
#define CP_WAIT(n)  asm volatile("cp.async.wait_group %0;" :: "n"(n) : "memory")

__device__ __forceinline__ void ldm_x4(uint32_t* r, uint32_t addr) {
    asm volatile("ldmatrix.sync.aligned.m8n8.x4.shared.b16 {%0,%1,%2,%3}, [%4];"
        : "=r"(r[0]), "=r"(r[1]), "=r"(r[2]), "=r"(r[3]) : "r"(addr));
}
__device__ __forceinline__ void ldm_x4_t(uint32_t* r, uint32_t addr) {
    asm volatile("ldmatrix.sync.aligned.m8n8.x4.trans.shared.b16 {%0,%1,%2,%3}, [%4];"
        : "=r"(r[0]), "=r"(r[1]), "=r"(r[2]), "=r"(r[3]) : "r"(addr));
}

__device__ __forceinline__ void mma_bf16(float* d, const uint32_t* a,
                                         uint32_t b0, uint32_t b1) {
    asm volatile(
        "mma.sync.aligned.m16n8k16.row.col.f32.bf16.bf16.f32 "
        "{%0,%1,%2,%3}, {%4,%5,%6,%7}, {%8,%9}, {%0,%1,%2,%3};"
        : "+f"(d[0]), "+f"(d[1]), "+f"(d[2]), "+f"(d[3])
        : "r"(a[0]), "r"(a[1]), "r"(a[2]), "r"(a[3]), "r"(b0), "r"(b1));
}

// ---------------------------------------------------------------------------
// fp32 -> (bf16 hi, bf16 lo) split
// ---------------------------------------------------------------------------
__global__ void split_bf16(const float* __restrict__ x,
                           __nv_bfloat16* __restrict__ hi,
                           __nv_bfloat16* __restrict__ lo, size_t n4)
{
    size_t i = (size_t)blockIdx.x * blockDim.x + threadIdx.x;
    if (i >= n4) return;
    float4 v = ((const float4*)x)[i];
    __nv_bfloat16 h0 = __float2bfloat16(v.x);
    __nv_bfloat16 h1 = __float2bfloat16(v.y);
    __nv_bfloat16 h2 = __float2bfloat16(v.z);
    __nv_bfloat16 h3 = __float2bfloat16(v.w);
    __nv_bfloat162 H0; H0.x = h0; H0.y = h1;
    __nv_bfloat162 H1; H1.x = h2; H1.y = h3;
    ((__nv_bfloat162*)hi)[2*i]   = H0;
    ((__nv_bfloat162*)hi)[2*i+1] = H1;
    __nv_bfloat162 L0, L1;
    L0.x = __float2bfloat16(v.x - __bfloat162float(h0));
    L0.y = __float2bfloat16(v.y - __bfloat162float(h1));
    L1.x = __float2bfloat16(v.z - __bfloat162float(h2));
    L1.y = __float2bfloat16(v.w - __bfloat162float(h3));
    ((__nv_bfloat162*)lo)[2*i]   = L0;
    ((__nv_bfloat162*)lo)[2*i+1] = L1;
}

// ---------------------------------------------------------------------------
// bf16x3 HMMA GEMM, 2 CTAs/SM:  C = A @ B^T
// CTA 128x128, 8 warps (4M x 2N), warp tile 32x64.
// BK=32, 2-stage cp.async pipeline, 80KB smem/CTA -> TWO independent CTAs
// per SM (separate barrier domains hide each other's sync/load phases).
// ROWB=80: 32 bf16 (64B) + 16B pad; 8-row ldmatrix offsets hit distinct banks.
// If Cf != nullptr -> fp32 output, else bf16 hi/lo split output.
// ---------------------------------------------------------------------------
#define BM 128
#define BN 128
#define BK 32
#define ROWB 80
#define TILEB (128 * ROWB)        // 10240
#define STAGEB (4 * TILEB)        // 40960
#define GEMM_SMEM (2 * STAGEB)    // 81920
#define GTHREADS 256

__global__ __launch_bounds__(GTHREADS, 2)
void gemm_hmma(const __nv_bfloat16* __restrict__ Ah, const __nv_bfloat16* __restrict__ Al,
               const __nv_bfloat16* __restrict__ Bh, const __nv_bfloat16* __restrict__ Bl,
               float* __restrict__ Cf,
               __nv_bfloat16* __restrict__ Ch, __nv_bfloat16* __restrict__ Cl,
               int M, int N, int K)
{
    extern __shared__ char smem[];
    const uint32_t sbase = smem_u32(smem);
    const int tid  = threadIdx.x;
    const int wid  = tid >> 5;
    const int lane = tid & 31;
    const int wm = wid & 3;          // M offset wm*32
    const int wn = wid >> 2;         // N offset wn*64
    const int m0 = blockIdx.x * BM;
    const int n0 = blockIdx.y * BN;
    const int NCH = K / BK;          // 160 for K=5120

    // stage loader: 2048 16B chunks, 8 per thread
    auto load_stage = [&](int s, int kc) {
        const int k0 = kc * BK;
#pragma unroll
        for (int j = 0; j < 8; j++) {
            int id   = tid + j * GTHREADS;   // 0..2047
            int tile = id >> 9;              // 0=Ah 1=Al 2=Bh 3=Bl
            int idx  = id & 511;
            int row  = idx >> 2;             // 0..127
            int c16  = idx & 3;              // 4 x 16B per 64B row
            const __nv_bfloat16* sb =
                (tile == 0) ? Ah : (tile == 1) ? Al : (tile == 2) ? Bh : Bl;
            int grow = ((tile < 2) ? m0 : n0) + row;
            const void* src = sb + (size_t)grow * K + k0 + c16 * 8;
            uint32_t dst = sbase + s * STAGEB + tile * TILEB + row * ROWB + c16 * 16;
            CP_ASYNC16(dst, src);
        }
        CP_COMMIT();
    };

    float acc[2][8][4];
#pragma unroll
    for (int mi = 0; mi < 2; mi++)
#pragma unroll
        for (int nj = 0; nj < 8; nj++)
#pragma unroll
            for (int q = 0; q < 4; q++) acc[mi][nj][q] = 0.f;

    load_stage(0, 0);
    if (NCH > 1) load_stage(1, 1);

    const int lr = lane & 15;
    const int lc = (lane >> 4) * 16;
    const uint32_t rowA = (wm * 32 + lr) * ROWB + lc;
    const uint32_t rowB = (wn * 64 + lr) * ROWB + lc;

    for (int c = 0; c < NCH; c++) {
        CP_WAIT(1);
        __syncthreads();

        const uint32_t st  = sbase + (c & 1) * STAGEB;
        const uint32_t sAh = st;
        const uint32_t sAl = st + TILEB;
        const uint32_t sBh = st + 2 * TILEB;
        const uint32_t sBl = st + 3 * TILEB;

#pragma unroll
        for (int kk = 0; kk < 2; kk++) {          // two k16 blocks (BK=32)
            const uint32_t koff = kk * 32;
            uint32_t ahf[2][4], alf[2][4];
#pragma unroll
            for (int mi = 0; mi < 2; mi++) {
                uint32_t ra = rowA + mi * 16 * ROWB + koff;
                ldm_x4(ahf[mi], sAh + ra);
                ldm_x4(alf[mi], sAl + ra);
            }
            // process B in halves to limit live registers
#pragma unroll
            for (int half = 0; half < 2; half++) {
                uint32_t bhf[2][4], blf[2][4];
#pragma unroll
                for (int nj = 0; nj < 2; nj++) {
                    uint32_t rb = rowB + (half * 2 + nj) * 16 * ROWB + koff;
                    ldm_x4(bhf[nj], sBh + rb);
                    ldm_x4(blf[nj], sBl + rb);
                }
                // term 1: Ah*Bh
#pragma unroll
                for (int mi = 0; mi < 2; mi++)
#pragma unroll
                    for (int nj = 0; nj < 2; nj++) {
                        const int njg = half * 2 + nj;
                        mma_bf16(acc[mi][2*njg],   ahf[mi], bhf[nj][0], bhf[nj][2]);
                        mma_bf16(acc[mi][2*njg+1], ahf[mi], bhf[nj][1], bhf[nj][3]);
                    }
                // term 2: Ah*Bl
#pragma unroll
                for (int mi = 0; mi < 2; mi++)
#pragma unroll
                    for (int nj = 0; nj < 2; nj++) {
                        const int njg = half * 2 + nj;
                        mma_bf16(acc[mi][2*njg],   ahf[mi], blf[nj][0], blf[nj][2]);
                        mma_bf16(acc[mi][2*njg+1], ahf[mi], blf[nj][1], blf[nj][3]);
                    }
                // term 3: Al*Bh
#pragma unroll
                for (int mi = 0; mi < 2; mi++)
#pragma unroll
                    for (int nj = 0; nj < 2; nj++) {
                        const int njg = half * 2 + nj;
                        mma_bf16(acc[mi][2*njg],   alf[mi], bhf[nj][0], bhf[nj][2]);
                        mma_bf16(acc[mi][2*njg+1], alf[mi], bhf[nj][1], bhf[nj][3]);
                    }
            }
        }

        __syncthreads();
        if (c + 2 < NCH) load_stage(c & 1, c + 2);
    }

    const int g  = lane >> 2;
    const int cc = (lane & 3) * 2;
#pragma unroll
    for (int mi = 0; mi < 2; mi++) {
        const int rbase = m0 + wm * 32 + mi * 16;
#pragma unroll
        for (int nj = 0; nj < 8; nj++) {
            const int cbase = n0 + wn * 64 + nj * 8 + cc;
            if (Cf) {
                float2 v0 = make_float2(acc[mi][nj][0], acc[mi][nj][1]);
                float2 v1 = make_float2(acc[mi][nj][2], acc[mi][nj][3]);
                *(float2*)&Cf[(size_t)(rbase + g) * N + cbase]     = v0;
                *(float2*)&Cf[(size_t)(rbase + g + 8) * N + cbase] = v1;
            } else {
#pragma unroll
                for (int rr = 0; rr < 2; rr++) {
                    float x0 = acc[mi][nj][2*rr], x1 = acc[mi][nj][2*rr+1];
                    __nv_bfloat16 h0 = __float2bfloat16(x0);
                    __nv_bfloat16 h1 = __float2bfloat16(x1);
                    __nv_bfloat162 H; H.x = h0; H.y = h1;
                    __nv_bfloat162 L;
                    L.x = __float2bfloat16(x0 - __bfloat162float(h0));
                    L.y = __float2bfloat16(x1 - __bfloat162float(h1));
                    size_t off = (size_t)(rbase + g + 8*rr) * N + cbase;
                    *(__nv_bfloat162*)&Ch[off] = H;
                    *(__nv_bfloat162*)&Cl[off] = L;
                }
            }
        }
    }
}

// ---------------------------------------------------------------------------
// HMMA flash attention (round 7, unchanged — 4331us config)
// ---------------------------------------------------------------------------
#define AROW 272
#define ATILE (64 * AROW)
#define PROW 144
#define PTILE (64 * PROW)
#define KSTAGE (4 * ATILE)
#define ATTN_SMEM (2*ATILE + 2*KSTAGE + 2*PTILE)

__global__ __launch_bounds__(128, 1)
void attn_hmma(const __nv_bfloat16* __restrict__ QKVh,
               const __nv_bfloat16* __restrict__ QKVl,
               __nv_bfloat16* __restrict__ Oh,
               __nv_bfloat16* __restrict__ Ol)
{
    extern __shared__ char smem[];
    const uint32_t sb = smem_u32(smem);
    const int tid = threadIdx.x, wid = tid >> 5, lane = tid & 31;
    const int qt = blockIdx.x, h = blockIdx.y, b = blockIdx.z;
    const int q0 = qt * 64;
    const int lr = lane & 15, lc = (lane >> 4) * 16;
    const int g = lane >> 2, t = lane & 3;

    const uint32_t QH_ = sb, QL_ = sb + ATILE;
    const uint32_t KST = sb + 2 * ATILE;
    const uint32_t PH_ = sb + 2 * ATILE + 2 * KSTAGE;
    const uint32_t PL_ = PH_ + PTILE;

#pragma unroll
    for (int j = 0; j < 8; j++) {
        int id = tid + j * 128;
        int row = id >> 4, c16 = id & 15;
        size_t goff = (size_t)(b * SEQ + q0 + row) * QKV_N + h * HDIM + c16 * 8;
        CP_ASYNC16(QH_ + row * AROW + c16 * 16, QKVh + goff);
        CP_ASYNC16(QL_ + row * AROW + c16 * 16, QKVl + goff);
    }
    CP_COMMIT();

    auto load_kv = [&](int s, int kt) {
        const uint32_t base = KST + s * KSTAGE;
        const int k0 = kt * 64;
#pragma unroll
        for (int j = 0; j < 8; j++) {
            int id = tid + j * 128;
            int row = id >> 4, c16 = id & 15;
            size_t grow = (size_t)(b * SEQ + k0 + row) * QKV_N;
            size_t koff = grow + HID     + h * HDIM + c16 * 8;
            size_t voff = grow + 2 * HID + h * HDIM + c16 * 8;
            uint32_t d = row * AROW + c16 * 16;
            CP_ASYNC16(base + d,             QKVh + koff);
            CP_ASYNC16(base + ATILE + d,     QKVl + koff);
            CP_ASYNC16(base + 2 * ATILE + d, QKVh + voff);
            CP_ASYNC16(base + 3 * ATILE + d, QKVl + voff);
        }
        CP_COMMIT();
    };

    load_kv(0, 0);

    const float LOG2E = 1.4426950408889634f;
    const float sscale = 0.08838834764831845f * LOG2E;
    const float slope = (h < 32) ? exp2f(-0.25f * (float)(h + 1))
                                 : exp2f(-0.125f * (float)(2 * (h - 32) + 1));
    const float slope2 = slope * LOG2E;

    const int row0 = q0 + wid * 16 + g;
    const int row1 = row0 + 8;

    float m0v = -1e30f, m1v = -1e30f, l0 = 0.f, l1 = 0.f;
    float o[16][4];
#pragma unroll
    for (int i = 0; i < 16; i++)
#pragma unroll
        for (int q = 0; q < 4; q++) o[i][q] = 0.f;

    for (int kt = 0; kt <= qt; kt++) {
        const bool more = (kt + 1 <= qt);
        if (more) load_kv((kt + 1) & 1, kt + 1);
        if (more) { CP_WAIT(1); } else { CP_WAIT(0); }
        __syncthreads();

        const uint32_t KB  = KST + (kt & 1) * KSTAGE;
        const uint32_t KHB = KB, KLB = KB + ATILE;
        const uint32_t VHB = KB + 2 * ATILE, VLB = KB + 3 * ATILE;

        float sacc[8][4];
#pragma unroll
        for (int nj = 0; nj < 8; nj++)
#pragma unroll
            for (int q = 0; q < 4; q++) sacc[nj][q] = 0.f;

#pragma unroll
        for (int dd = 0; dd < 8; dd++) {
            const uint32_t ra = (wid * 16 + lr) * AROW + dd * 32 + lc;
            uint32_t qhf[4], qlf[4];
            ldm_x4(qhf, QH_ + ra);
            ldm_x4(qlf, QL_ + ra);
            uint32_t khf[4][4], klf[4][4];
#pragma unroll
            for (int v = 0; v < 4; v++) {
                const uint32_t rb = (v * 16 + lr) * AROW + dd * 32 + lc;
                ldm_x4(khf[v], KHB + rb);
                ldm_x4(klf[v], KLB + rb);
            }
#pragma unroll
            for (int v = 0; v < 4; v++) {
                mma_bf16(sacc[2*v],   qhf, khf[v][0], khf[v][2]);
                mma_bf16(sacc[2*v+1], qhf, khf[v][1], khf[v][3]);
            }
#pragma unroll
            for (int v = 0; v < 4; v++) {
                mma_bf16(sacc[2*v],   qhf, klf[v][0], klf[v][2]);
                mma_bf16(sacc[2*v+1], qhf, klf[v][1], klf[v][3]);
            }
#pragma unroll
            for (int v = 0; v < 4; v++) {
                mma_bf16(sacc[2*v],   qlf, khf[v][0], khf[v][2]);
                mma_bf16(sacc[2*v+1], qlf, khf[v][1], khf[v][3]);
            }
        }

        const int k0 = kt * 64;
        const bool diag = (kt == qt);
        float rmax0 = -1e30f, rmax1 = -1e30f;
#pragma unroll
        for (int nj = 0; nj < 8; nj++) {
#pragma unroll
            for (int e = 0; e < 2; e++) {
                const int col = k0 + nj * 8 + 2 * t + e;
                float v0 = sacc[nj][e]     * sscale + slope2 * (float)col;
                float v1 = sacc[nj][2 + e] * sscale + slope2 * (float)col;
                if (diag) {
                    if (col > row0) v0 = -1e30f;
                    if (col > row1) v1 = -1e30f;
                }
                sacc[nj][e] = v0; sacc[nj][2 + e] = v1;
                rmax0 = fmaxf(rmax0, v0); rmax1 = fmaxf(rmax1, v1);
            }
        }
        rmax0 = fmaxf(rmax0, __shfl_xor_sync(0xffffffffu, rmax0, 1));
        rmax0 = fmaxf(rmax0, __shfl_xor_sync(0xffffffffu, rmax0, 2));
        rmax1 = fmaxf(rmax1, __shfl_xor_sync(0xffffffffu, rmax1, 1));
        rmax1 = fmaxf(rmax1, __shfl_xor_sync(0xffffffffu, rmax1, 2));

        const float mn0 = fmaxf(m0v, rmax0), mn1 = fmaxf(m1v, rmax1);
        const float al0 = exp2f(m0v - mn0),  al1 = exp2f(m1v - mn1);
        m0v = mn0; m1v = mn1;

        float ps0 = 0.f, ps1 = 0.f;
#pragma unroll
        for (int nj = 0; nj < 8; nj++) {
#pragma unroll
            for (int e = 0; e < 2; e++) {
                float p0 = exp2f(sacc[nj][e]     - mn0);
                float p1 = exp2f(sacc[nj][2 + e] - mn1);
                sacc[nj][e] = p0; sacc[nj][2 + e] = p1;
                ps0 += p0; ps1 += p1;
            }
        }
        ps0 += __shfl_xor_sync(0xffffffffu, ps0, 1);
        ps0 += __shfl_xor_sync(0xffffffffu, ps0, 2);
        ps1 += __shfl_xor_sync(0xffffffffu, ps1, 1);
        ps1 += __shfl_xor_sync(0xffffffffu, ps1, 2);
        l0 = l0 * al0 + ps0;
        l1 = l1 * al1 + ps1;

#pragma unroll
        for (int i = 0; i < 16; i++) {
            o[i][0] *= al0; o[i][1] *= al0;
            o[i][2] *= al1; o[i][3] *= al1;
        }

#pragma unroll
        for (int nj = 0; nj < 8; nj++) {
#pragma unroll
            for (int rr = 0; rr < 2; rr++) {
                float x0 = sacc[nj][2*rr], x1 = sacc[nj][2*rr + 1];
                __nv_bfloat16 h0 = __float2bfloat16(x0);
                __nv_bfloat16 h1 = __float2bfloat16(x1);
                __nv_bfloat162 H; H.x = h0; H.y = h1;
                __nv_bfloat162 L;
                L.x = __float2bfloat16(x0 - __bfloat162float(h0));
                L.y = __float2bfloat16(x1 - __bfloat162float(h1));
                uint32_t off = (wid * 16 + g + 8 * rr) * PROW + (nj * 8 + 2 * t) * 2;
                *(__nv_bfloat162*)(smem + (PH_ - sb) + off) = H;
                *(__nv_bfloat162*)(smem + (PL_ - sb) + off) = L;
            }
        }
        __syncwarp();

#pragma unroll
        for (int ks = 0; ks < 4; ks++) {
            const uint32_t pa = (wid * 16 + lr) * PROW + ks * 32 + lc;
            uint32_t phf[4], plf[4];
            ldm_x4(phf, PH_ + pa);
            ldm_x4(plf, PL_ + pa);
#pragma unroll
            for (int nn = 0; nn < 8; nn++) {
                const uint32_t va = (ks * 16 + lr) * AROW + nn * 32 + lc;
                uint32_t vhf[4], vlf[4];
                ldm_x4_t(vhf, VHB + va);
                ldm_x4_t(vlf, VLB + va);
                mma_bf16(o[2*nn],   phf, vhf[0], vhf[1]);
                mma_bf16(o[2*nn+1], phf, vhf[2], vhf[3]);
                mma_bf16(o[2*nn],   phf, vlf[0], vlf[1]);
                mma_bf16(o[2*nn+1], phf, vlf[2], vlf[3]);
                mma_bf16(o[2*nn],   plf, vhf[0], vhf[1]);
                mma_bf16(o[2*nn+1], plf, vhf[2], vhf[3]);
            }
        }
        __syncthreads();
    }

    const float inv0 = 1.0f / l0, inv1 = 1.0f / l1;
#pragma unroll
    for (int i = 0; i < 16; i++) {
        const int col = h * HDIM + i * 8 + 2 * t;
#pragma unroll
        for (int rr = 0; rr < 2; rr++) {
            const float inv = rr ? inv1 : inv0;
            const int row = rr ? row1 : row0;
            float x0 = o[i][2*rr] * inv, x1 = o[i][2*rr + 1] * inv;
            __nv_bfloat16 h0 = __float2bfloat16(x0);
            __nv_bfloat16 h1 = __float2bfloat16(x1);
            __nv_bfloat162 H; H.x = h0; H.y = h1;
            __nv_bfloat162 L;
            L.x = __float2bfloat16(x0 - __bfloat162float(h0));
            L.y = __float2bfloat16(x1 - __bfloat162float(h1));
            size_t off = (size_t)(b * SEQ + row) * HID + col;
            *(__nv_bfloat162*)&Oh[off] = H;
            *(__nv_bfloat162*)&Ol[off] = L;
        }
    }
}

// ---------------------------------------------------------------------------
// Launch
// ---------------------------------------------------------------------------
extern "C" void kernel_launch(void* const* d_in, const int* in_sizes, int n_in,
                              void* d_out, int out_size)
{
    const float* hidden = (const float*)d_in[0];
    const float* W_pack = (const float*)d_in[1];
    const float* W_o    = (const float*)d_in[2];
    float* out = (float*)d_out;

    __nv_bfloat16 *qkvh, *qkvl, *hh, *hl, *ah, *al, *wph, *wpl, *woh, *wol;
    cudaGetSymbolAddress((void**)&qkvh, g_qkvh);
    cudaGetSymbolAddress((void**)&qkvl, g_qkvl);
    cudaGetSymbolAddress((void**)&hh,  g_hh);
    cudaGetSymbolAddress((void**)&hl,  g_hl);
    cudaGetSymbolAddress((void**)&ah,  g_ah);
    cudaGetSymbolAddress((void**)&al,  g_al);
    cudaGetSymbolAddress((void**)&wph, g_wph);
    cudaGetSymbolAddress((void**)&wpl, g_wpl);
    cudaGetSymbolAddress((void**)&woh, g_woh);
    cudaGetSymbolAddress((void**)&wol, g_wol);

    cudaFuncSetAttribute(gemm_hmma, cudaFuncAttributeMaxDynamicSharedMemorySize,
                         GEMM_SMEM);
    cudaFuncSetAttribute(attn_hmma, cudaFuncAttributeMaxDynamicSharedMemorySize,
                         ATTN_SMEM);

    {
        size_t n4;
        n4 = (size_t)QKV_N * HID / 4;
        split_bf16<<<(unsigned)((n4 + 255) / 256), 256>>>(W_pack, wph, wpl, n4);
        n4 = (size_t)HID * HID / 4;
        split_bf16<<<(unsigned)((n4 + 255) / 256), 256>>>(W_o, woh, wol, n4);
        n4 = (size_t)MROWS * HID / 4;
        split_bf16<<<(unsigned)((n4 + 255) / 256), 256>>>(hidden, hh, hl, n4);
    }

    // GEMM1: qkv = hidden @ W_pack^T, bf16 hi/lo output
    gemm_hmma<<<dim3(MROWS/BM, QKV_N/BN), GTHREADS, GEMM_SMEM>>>(
        hh, hl, wph, wpl, nullptr, qkvh, qkvl, MROWS, QKV_N, HID);

    // Attention
    attn_hmma<<<dim3(SEQ/64, NHEAD, BATCH), 128, ATTN_SMEM>>>(qkvh, qkvl, ah, al);

    // GEMM2: out = attn @ W_o^T, fp32 output
    gemm_hmma<<<dim3(MROWS/BM, HID/BN), GTHREADS, GEMM_SMEM>>>(
        ah, al, woh, wol, out, nullptr, nullptr, MROWS, HID, HID);
}

// round 10
// speedup vs baseline: 1.4196x; 1.3960x over previous
#include <cuda_runtime.h>
#include <cuda_fp16.h>
#include <math.h>
#include <stdint.h>

// Problem constants
#define BATCH 2
#define SEQ   1024
#define HID   5120
#define NHEAD 40
#define HDIM  128
#define QKV_N (3*HID)          // 15360
#define MROWS (BATCH*SEQ)      // 2048

// ---------------------------------------------------------------------------
// Scratch (fp16)
// ---------------------------------------------------------------------------
__device__ __half g_qkvh[(size_t)MROWS * QKV_N];
__device__ __half g_qkvl[(size_t)MROWS * HID];     // lo only needed for Q region
__device__ __half g_hh[(size_t)MROWS * HID];
__device__ __half g_hl[(size_t)MROWS * HID];
__device__ __half g_ah[(size_t)MROWS * HID];
__device__ __half g_al[(size_t)MROWS * HID];
__device__ __half g_wph[(size_t)QKV_N * HID];
__device__ __half g_woh[(size_t)HID * HID];

// ---------------------------------------------------------------------------
// PTX helpers (compute_103-safe)
// ---------------------------------------------------------------------------
__device__ __forceinline__ uint32_t smem_u32(const void* p) {
    uint32_t a;
    asm("{ .reg .u64 t; cvta.to.shared.u64 t, %1; cvt.u32.u64 %0, t; }"
        : "=r"(a) : "l"(p));
    return a;
}

#define CP_ASYNC16(dst, src) \
    asm volatile("cp.async.cg.shared.global [%0], [%1], 16;" \
        :: "r"(dst), "l"(src))
#define CP_COMMIT() asm volatile("cp.async.commit_group;" ::: "memory")
#define CP_WAIT(n)  asm volatile("cp.async.wait_group %0;" :: "n"(n) : "memory")

__device__ __forceinline__ void ldm_x4(uint32_t* r, uint32_t addr) {
    asm volatile("ldmatrix.sync.aligned.m8n8.x4.shared.b16 {%0,%1,%2,%3}, [%4];"
        : "=r"(r[0]), "=r"(r[1]), "=r"(r[2]), "=r"(r[3]) : "r"(addr));
}
__device__ __forceinline__ void ldm_x4_t(uint32_t* r, uint32_t addr) {
    asm volatile("ldmatrix.sync.aligned.m8n8.x4.trans.shared.b16 {%0,%1,%2,%3}, [%4];"
        : "=r"(r[0]), "=r"(r[1]), "=r"(r[2]), "=r"(r[3]) : "r"(addr));
}

__device__ __forceinline__ void mma_f16(float* d, const uint32_t* a,
                                        uint32_t b0, uint32_t b1) {
    asm volatile(
        "mma.sync.aligned.m16n8k16.row.col.f32.f16.f16.f32 "
        "{%0,%1,%2,%3}, {%4,%5,%6,%7}, {%8,%9}, {%0,%1,%2,%3};"
        : "+f"(d[0]), "+f"(d[1]), "+f"(d[2]), "+f"(d[3])
        : "r"(a[0]), "r"(a[1]), "r"(a[2]), "r"(a[3]), "r"(b0), "r"(b1));
}

// ---------------------------------------------------------------------------
// fp32 -> fp16 hi+lo split / hi-only convert
// ---------------------------------------------------------------------------
__global__ void split_f16(const float* __restrict__ x,
                          __half* __restrict__ hi,
                          __half* __restrict__ lo, size_t n4)
{
    size_t i = (size_t)blockIdx.x * blockDim.x + threadIdx.x;
    if (i >= n4) return;
    float4 v = ((const float4*)x)[i];
    __half h0 = __float2half_rn(v.x);
    __half h1 = __float2half_rn(v.y);
    __half h2 = __float2half_rn(v.z);
    __half h3 = __float2half_rn(v.w);
    __half2 H0; H0.x = h0; H0.y = h1;
    __half2 H1; H1.x = h2; H1.y = h3;
    ((__half2*)hi)[2*i]   = H0;
    ((__half2*)hi)[2*i+1] = H1;
    __half2 L0, L1;
    L0.x = __float2half_rn(v.x - __half2float(h0));
    L0.y = __float2half_rn(v.y - __half2float(h1));
    L1.x = __float2half_rn(v.z - __half2float(h2));
    L1.y = __float2half_rn(v.w - __half2float(h3));
    ((__half2*)lo)[2*i]   = L0;
    ((__half2*)lo)[2*i+1] = L1;
}

__global__ void cvt_f16(const float* __restrict__ x,
                        __half* __restrict__ hi, size_t n4)
{
    size_t i = (size_t)blockIdx.x * blockDim.x + threadIdx.x;
    if (i >= n4) return;
    float4 v = ((const float4*)x)[i];
    __half2 H0; H0.x = __float2half_rn(v.x); H0.y = __float2half_rn(v.y);
    __half2 H1; H1.x = __float2half_rn(v.z); H1.y = __float2half_rn(v.w);
    ((__half2*)hi)[2*i]   = H0;
    ((__half2*)hi)[2*i+1] = H1;
}

// ---------------------------------------------------------------------------
// fp16 2-term HMMA GEMM:  C = A @ B^T ≈ (Ah+Al)·Bh
// CTA 128x128, 8 warps (4M x 2N), warp tile 32x64, BK=32,
// 2-stage cp.async, 60KB smem -> 2 CTAs/SM.
// 32 MMAs per k16 block vs 48 in bf16x3.
// Cf != nullptr -> fp32 out; else fp16 hi/lo out (Cl only for col < lo_limit).
// ---------------------------------------------------------------------------
#define BM 128
#define BN 128
#define BK 32
#define ROWB 80
#define TILEB (128 * ROWB)        // 10240
#define STAGEB (3 * TILEB)        // 30720 (Ah, Al, Bh)
#define GEMM_SMEM (2 * STAGEB)    // 61440
#define GTHREADS 256

__global__ __launch_bounds__(GTHREADS, 2)
void gemm_hmma(const __half* __restrict__ Ah, const __half* __restrict__ Al,
               const __half* __restrict__ Bh,
               float* __restrict__ Cf,
               __half* __restrict__ Ch, __half* __restrict__ Cl, int lo_limit,
               int M, int N, int K)
{
    extern __shared__ char smem[];
    const uint32_t sbase = smem_u32(smem);
    const int tid  = threadIdx.x;
    const int wid  = tid >> 5;
    const int lane = tid & 31;
    const int wm = wid & 3;
    const int wn = wid >> 2;
    const int m0 = blockIdx.x * BM;
    const int n0 = blockIdx.y * BN;
    const int NCH = K / BK;

    // stage loader: 1536 16B chunks, 6 per thread
    auto load_stage = [&](int s, int kc) {
        const int k0 = kc * BK;
#pragma unroll
        for (int j = 0; j < 6; j++) {
            int id   = tid + j * GTHREADS;   // 0..1535
            int tile = id >> 9;              // 0=Ah 1=Al 2=Bh
            int idx  = id & 511;
            int row  = idx >> 2;
            int c16  = idx & 3;
            const __half* sb = (tile == 0) ? Ah : (tile == 1) ? Al : Bh;
            int grow = ((tile < 2) ? m0 : n0) + row;
            const void* src = sb + (size_t)grow * K + k0 + c16 * 8;
            uint32_t dst = sbase + s * STAGEB + tile * TILEB + row * ROWB + c16 * 16;
            CP_ASYNC16(dst, src);
        }
        CP_COMMIT();
    };

    float acc[2][8][4];
#pragma unroll
    for (int mi = 0; mi < 2; mi++)
#pragma unroll
        for (int nj = 0; nj < 8; nj++)
#pragma unroll
            for (int q = 0; q < 4; q++) acc[mi][nj][q] = 0.f;

    load_stage(0, 0);
    if (NCH > 1) load_stage(1, 1);

    const int lr = lane & 15;
    const int lc = (lane >> 4) * 16;
    const uint32_t rowA = (wm * 32 + lr) * ROWB + lc;
    const uint32_t rowB = (wn * 64 + lr) * ROWB + lc;

    for (int c = 0; c < NCH; c++) {
        CP_WAIT(1);
        __syncthreads();

        const uint32_t st  = sbase + (c & 1) * STAGEB;
        const uint32_t sAh = st;
        const uint32_t sAl = st + TILEB;
        const uint32_t sBh = st + 2 * TILEB;

#pragma unroll
        for (int kk = 0; kk < 2; kk++) {
            const uint32_t koff = kk * 32;
            uint32_t ahf[2][4], alf[2][4], bhf[4][4];
#pragma unroll
            for (int mi = 0; mi < 2; mi++) {
                uint32_t ra = rowA + mi * 16 * ROWB + koff;
                ldm_x4(ahf[mi], sAh + ra);
                ldm_x4(alf[mi], sAl + ra);
            }
#pragma unroll
            for (int nj = 0; nj < 4; nj++) {
                uint32_t rb = rowB + nj * 16 * ROWB + koff;
                ldm_x4(bhf[nj], sBh + rb);
            }
            // term 1: Ah * Bh
#pragma unroll
            for (int mi = 0; mi < 2; mi++)
#pragma unroll
                for (int nj = 0; nj < 4; nj++) {
                    mma_f16(acc[mi][2*nj],   ahf[mi], bhf[nj][0], bhf[nj][2]);
                    mma_f16(acc[mi][2*nj+1], ahf[mi], bhf[nj][1], bhf[nj][3]);
                }
            // term 2: Al * Bh
#pragma unroll
            for (int mi = 0; mi < 2; mi++)
#pragma unroll
                for (int nj = 0; nj < 4; nj++) {
                    mma_f16(acc[mi][2*nj],   alf[mi], bhf[nj][0], bhf[nj][2]);
                    mma_f16(acc[mi][2*nj+1], alf[mi], bhf[nj][1], bhf[nj][3]);
                }
        }

        __syncthreads();
        if (c + 2 < NCH) load_stage(c & 1, c + 2);
    }

    const int g  = lane >> 2;
    const int cc = (lane & 3) * 2;
#pragma unroll
    for (int mi = 0; mi < 2; mi++) {
        const int rbase = m0 + wm * 32 + mi * 16;
#pragma unroll
        for (int nj = 0; nj < 8; nj++) {
            const int cbase = n0 + wn * 64 + nj * 8 + cc;
            if (Cf) {
                float2 v0 = make_float2(acc[mi][nj][0], acc[mi][nj][1]);
                float2 v1 = make_float2(acc[mi][nj][2], acc[mi][nj][3]);
                *(float2*)&Cf[(size_t)(rbase + g) * N + cbase]     = v0;
                *(float2*)&Cf[(size_t)(rbase + g + 8) * N + cbase] = v1;
            } else {
#pragma unroll
                for (int rr = 0; rr < 2; rr++) {
                    float x0 = acc[mi][nj][2*rr], x1 = acc[mi][nj][2*rr+1];
                    __half h0 = __float2half_rn(x0);
                    __half h1 = __float2half_rn(x1);
                    __half2 H; H.x = h0; H.y = h1;
                    size_t row = (size_t)(rbase + g + 8*rr);
                    *(__half2*)&Ch[row * N + cbase] = H;
                    if (cbase < lo_limit) {
                        __half2 L;
                        L.x = __float2half_rn(x0 - __half2float(h0));
                        L.y = __float2half_rn(x1 - __half2float(h1));
                        *(__half2*)&Cl[row * lo_limit + cbase] = L;
                    }
                }
            }
        }
    }
}

// ---------------------------------------------------------------------------
// fp16 2-term HMMA flash attention: S = (Qh+Ql)·Kh, O = (Ph+Pl)·Vh
// CTA: 4 warps, 64 q-rows. K/V hi-only tiles, double-buffered.
// ---------------------------------------------------------------------------
#define AROW 272                       // 128 fp16 = 256B + 16B pad
#define ATILE (64 * AROW)              // 17408
#define PROW 144
#define PTILE (64 * PROW)              // 9216
#define KSTAGE (2 * ATILE)             // kh, vh = 34816
#define ATTN_SMEM (2*ATILE + 2*KSTAGE + 2*PTILE)   // 122880

__global__ __launch_bounds__(128, 1)
void attn_hmma(const __half* __restrict__ QKVh,
               const __half* __restrict__ Ql_,
               __half* __restrict__ Oh,
               __half* __restrict__ Ol)
{
    extern __shared__ char smem[];
    const uint32_t sb = smem_u32(smem);
    const int tid = threadIdx.x, wid = tid >> 5, lane = tid & 31;
    const int qt = blockIdx.x, h = blockIdx.y, b = blockIdx.z;
    const int q0 = qt * 64;
    const int lr = lane & 15, lc = (lane >> 4) * 16;
    const int g = lane >> 2, t = lane & 3;

    const uint32_t QH_ = sb, QL_ = sb + ATILE;
    const uint32_t KST = sb + 2 * ATILE;
    const uint32_t PH_ = sb + 2 * ATILE + 2 * KSTAGE;
    const uint32_t PL_ = PH_ + PTILE;

    // load Q hi (from qkvh) and Q lo (from dedicated Q-lo array, stride HID)
#pragma unroll
    for (int j = 0; j < 8; j++) {
        int id = tid + j * 128;
        int row = id >> 4, c16 = id & 15;
        size_t ghoff = (size_t)(b * SEQ + q0 + row) * QKV_N + h * HDIM + c16 * 8;
        size_t gloff = (size_t)(b * SEQ + q0 + row) * HID   + h * HDIM + c16 * 8;
        CP_ASYNC16(QH_ + row * AROW + c16 * 16, QKVh + ghoff);
        CP_ASYNC16(QL_ + row * AROW + c16 * 16, Ql_  + gloff);
    }
    CP_COMMIT();

    auto load_kv = [&](int s, int kt) {
        const uint32_t base = KST + s * KSTAGE;
        const int k0 = kt * 64;
#pragma unroll
        for (int j = 0; j < 8; j++) {
            int id = tid + j * 128;
            int row = id >> 4, c16 = id & 15;
            size_t grow = (size_t)(b * SEQ + k0 + row) * QKV_N;
            size_t koff = grow + HID     + h * HDIM + c16 * 8;
            size_t voff = grow + 2 * HID + h * HDIM + c16 * 8;
            uint32_t d = row * AROW + c16 * 16;
            CP_ASYNC16(base + d,         QKVh + koff);
            CP_ASYNC16(base + ATILE + d, QKVh + voff);
        }
        CP_COMMIT();
    };

    load_kv(0, 0);

    const float LOG2E = 1.4426950408889634f;
    const float sscale = 0.08838834764831845f * LOG2E;
    const float slope = (h < 32) ? exp2f(-0.25f * (float)(h + 1))
                                 : exp2f(-0.125f * (float)(2 * (h - 32) + 1));
    const float slope2 = slope * LOG2E;

    const int row0 = q0 + wid * 16 + g;
    const int row1 = row0 + 8;

    float m0v = -1e30f, m1v = -1e30f, l0 = 0.f, l1 = 0.f;
    float o[16][4];
#pragma unroll
    for (int i = 0; i < 16; i++)
#pragma unroll
        for (int q = 0; q < 4; q++) o[i][q] = 0.f;

    for (int kt = 0; kt <= qt; kt++) {
        const bool more = (kt + 1 <= qt);
        if (more) load_kv((kt + 1) & 1, kt + 1);
        if (more) { CP_WAIT(1); } else { CP_WAIT(0); }
        __syncthreads();

        const uint32_t KB  = KST + (kt & 1) * KSTAGE;
        const uint32_t KHB = KB;
        const uint32_t VHB = KB + ATILE;

        float sacc[8][4];
#pragma unroll
        for (int nj = 0; nj < 8; nj++)
#pragma unroll
            for (int q = 0; q < 4; q++) sacc[nj][q] = 0.f;

#pragma unroll
        for (int dd = 0; dd < 8; dd++) {
            const uint32_t ra = (wid * 16 + lr) * AROW + dd * 32 + lc;
            uint32_t qhf[4], qlf[4];
            ldm_x4(qhf, QH_ + ra);
            ldm_x4(qlf, QL_ + ra);
            uint32_t khf[4][4];
#pragma unroll
            for (int v = 0; v < 4; v++) {
                const uint32_t rb = (v * 16 + lr) * AROW + dd * 32 + lc;
                ldm_x4(khf[v], KHB + rb);
            }
#pragma unroll
            for (int v = 0; v < 4; v++) {
                mma_f16(sacc[2*v],   qhf, khf[v][0], khf[v][2]);
                mma_f16(sacc[2*v+1], qhf, khf[v][1], khf[v][3]);
            }
#pragma unroll
            for (int v = 0; v < 4; v++) {
                mma_f16(sacc[2*v],   qlf, khf[v][0], khf[v][2]);
                mma_f16(sacc[2*v+1], qlf, khf[v][1], khf[v][3]);
            }
        }

        const int k0 = kt * 64;
        const bool diag = (kt == qt);
        float rmax0 = -1e30f, rmax1 = -1e30f;
#pragma unroll
        for (int nj = 0; nj < 8; nj++) {
#pragma unroll
            for (int e = 0; e < 2; e++) {
                const int col = k0 + nj * 8 + 2 * t + e;
                float v0 = sacc[nj][e]     * sscale + slope2 * (float)col;
                float v1 = sacc[nj][2 + e] * sscale + slope2 * (float)col;
                if (diag) {
                    if (col > row0) v0 = -1e30f;
                    if (col > row1) v1 = -1e30f;
                }
                sacc[nj][e] = v0; sacc[nj][2 + e] = v1;
                rmax0 = fmaxf(rmax0, v0); rmax1 = fmaxf(rmax1, v1);
            }
        }
        rmax0 = fmaxf(rmax0, __shfl_xor_sync(0xffffffffu, rmax0, 1));
        rmax0 = fmaxf(rmax0, __shfl_xor_sync(0xffffffffu, rmax0, 2));
        rmax1 = fmaxf(rmax1, __shfl_xor_sync(0xffffffffu, rmax1, 1));
        rmax1 = fmaxf(rmax1, __shfl_xor_sync(0xffffffffu, rmax1, 2));

        const float mn0 = fmaxf(m0v, rmax0), mn1 = fmaxf(m1v, rmax1);
        const float al0 = exp2f(m0v - mn0),  al1 = exp2f(m1v - mn1);
        m0v = mn0; m1v = mn1;

        float ps0 = 0.f, ps1 = 0.f;
#pragma unroll
        for (int nj = 0; nj < 8; nj++) {
#pragma unroll
            for (int e = 0; e < 2; e++) {
                float p0 = exp2f(sacc[nj][e]     - mn0);
                float p1 = exp2f(sacc[nj][2 + e] - mn1);
                sacc[nj][e] = p0; sacc[nj][2 + e] = p1;
                ps0 += p0; ps1 += p1;
            }
        }
        ps0 += __shfl_xor_sync(0xffffffffu, ps0, 1);
        ps0 += __shfl_xor_sync(0xffffffffu, ps0, 2);
        ps1 += __shfl_xor_sync(0xffffffffu, ps1, 1);
        ps1 += __shfl_xor_sync(0xffffffffu, ps1, 2);
        l0 = l0 * al0 + ps0;
        l1 = l1 * al1 + ps1;

#pragma unroll
        for (int i = 0; i < 16; i++) {
            o[i][0] *= al0; o[i][1] *= al0;
            o[i][2] *= al1; o[i][3] *= al1;
        }

        // write P hi/lo (fp16) to smem
#pragma unroll
        for (int nj = 0; nj < 8; nj++) {
#pragma unroll
            for (int rr = 0; rr < 2; rr++) {
                float x0 = sacc[nj][2*rr], x1 = sacc[nj][2*rr + 1];
                __half h0 = __float2half_rn(x0);
                __half h1 = __float2half_rn(x1);
                __half2 H; H.x = h0; H.y = h1;
                __half2 L;
                L.x = __float2half_rn(x0 - __half2float(h0));
                L.y = __float2half_rn(x1 - __half2float(h1));
                uint32_t off = (wid * 16 + g + 8 * rr) * PROW + (nj * 8 + 2 * t) * 2;
                *(__half2*)(smem + (PH_ - sb) + off) = H;
                *(__half2*)(smem + (PL_ - sb) + off) = L;
            }
        }
        __syncwarp();

        // O += (Ph+Pl) * Vh
#pragma unroll
        for (int ks = 0; ks < 4; ks++) {
            const uint32_t pa = (wid * 16 + lr) * PROW + ks * 32 + lc;
            uint32_t phf[4], plf[4];
            ldm_x4(phf, PH_ + pa);
            ldm_x4(plf, PL_ + pa);
#pragma unroll
            for (int nn = 0; nn < 8; nn++) {
                const uint32_t va = (ks * 16 + lr) * AROW + nn * 32 + lc;
                uint32_t vhf[4];
                ldm_x4_t(vhf, VHB + va);
                mma_f16(o[2*nn],   phf, vhf[0], vhf[1]);
                mma_f16(o[2*nn+1], phf, vhf[2], vhf[3]);
                mma_f16(o[2*nn],   plf, vhf[0], vhf[1]);
                mma_f16(o[2*nn+1], plf, vhf[2], vhf[3]);
            }
        }
        __syncthreads();
    }

    const float inv0 = 1.0f / l0, inv1 = 1.0f / l1;
#pragma unroll
    for (int i = 0; i < 16; i++) {
        const int col = h * HDIM + i * 8 + 2 * t;
#pragma unroll
        for (int rr = 0; rr < 2; rr++) {
            const float inv = rr ? inv1 : inv0;
            const int row = rr ? row1 : row0;
            float x0 = o[i][2*rr] * inv, x1 = o[i][2*rr + 1] * inv;
            __half h0 = __float2half_rn(x0);
            __half h1 = __float2half_rn(x1);
            __half2 H; H.x = h0; H.y = h1;
            __half2 L;
            L.x = __float2half_rn(x0 - __half2float(h0));
            L.y = __float2half_rn(x1 - __half2float(h1));
            size_t off = (size_t)(b * SEQ + row) * HID + col;
            *(__half2*)&Oh[off] = H;
            *(__half2*)&Ol[off] = L;
        }
    }
}

// ---------------------------------------------------------------------------
// Launch
// ---------------------------------------------------------------------------
extern "C" void kernel_launch(void* const* d_in, const int* in_sizes, int n_in,
                              void* d_out, int out_size)
{
    const float* hidden = (const float*)d_in[0];
    const float* W_pack = (const float*)d_in[1];
    const float* W_o    = (const float*)d_in[2];
    float* out = (float*)d_out;

    __half *qkvh, *qkvl, *hh, *hl, *ah, *al, *wph, *woh;
    cudaGetSymbolAddress((void**)&qkvh, g_qkvh);
    cudaGetSymbolAddress((void**)&qkvl, g_qkvl);
    cudaGetSymbolAddress((void**)&hh,  g_hh);
    cudaGetSymbolAddress((void**)&hl,  g_hl);
    cudaGetSymbolAddress((void**)&ah,  g_ah);
    cudaGetSymbolAddress((void**)&al,  g_al);
    cudaGetSymbolAddress((void**)&wph, g_wph);
    cudaGetSymbolAddress((void**)&woh, g_woh);

    cudaFuncSetAttribute(gemm_hmma, cudaFuncAttributeMaxDynamicSharedMemorySize,
                         GEMM_SMEM);
    cudaFuncSetAttribute(attn_hmma, cudaFuncAttributeMaxDynamicSharedMemorySize,
                         ATTN_SMEM);

    {
        size_t n4;
        n4 = (size_t)QKV_N * HID / 4;
        cvt_f16<<<(unsigned)((n4 + 255) / 256), 256>>>(W_pack, wph, n4);
        n4 = (size_t)HID * HID / 4;
        cvt_f16<<<(unsigned)((n4 + 255) / 256), 256>>>(W_o, woh, n4);
        n4 = (size_t)MROWS * HID / 4;
        split_f16<<<(unsigned)((n4 + 255) / 256), 256>>>(hidden, hh, hl, n4);
    }

    // GEMM1: qkv = hidden @ W_pack^T, fp16 hi out; lo only for Q columns
    gemm_hmma<<<dim3(MROWS/BM, QKV_N/BN), GTHREADS, GEMM_SMEM>>>(
        hh, hl, wph, nullptr, qkvh, qkvl, HID, MROWS, QKV_N, HID);

    // Attention (fp16 2-term flash, computed ALiBi)
    attn_hmma<<<dim3(SEQ/64, NHEAD, BATCH), 128, ATTN_SMEM>>>(qkvh, qkvl, ah, al);

    // GEMM2: out = attn @ W_o^T, fp32 out
    gemm_hmma<<<dim3(MROWS/BM, HID/BN), GTHREADS, GEMM_SMEM>>>(
        ah, al, woh, out, nullptr, nullptr, 0, MROWS, HID, HID);
}